// round 8
// baseline (speedup 1.0000x reference)
#include <cuda_runtime.h>

#define Bq   256
#define Tq   1024
#define NUMq 126
#define LBLq 128

__device__ int d_perm[Bq];

// Rank sequences by length (desc). CTA i runs ranks i and 255-i together, so
// the pairing is placement-independent.
__global__ void rank_kernel(const int* __restrict__ lens) {
    __shared__ int sl[Bq];
    int i = threadIdx.x;
    int li = lens[i];
    sl[i] = li;
    __syncthreads();
    int r = 0;
    #pragma unroll 8
    for (int k = 0; k < Bq; ++k) {
        int lk = sl[k];
        r += (lk > li) || (lk == li && k < i);
    }
    d_perm[r] = i;
}

__device__ __forceinline__ void fma2(unsigned long long& d,
                                     unsigned long long a, unsigned long long b) {
    asm("fma.rn.f32x2 %0, %1, %2, %0;" : "+l"(d) : "l"(a), "l"(b));
}
__device__ __forceinline__ unsigned long long add2(unsigned long long a,
                                                   unsigned long long b) {
    unsigned long long d;
    asm("add.rn.f32x2 %0, %1, %2;" : "=l"(d) : "l"(a), "l"(b));
    return d;
}
__device__ __forceinline__ unsigned long long pack2(float lo, float hi) {
    unsigned long long d;
    asm("mov.b64 %0, {%1, %2};" : "=l"(d) : "f"(lo), "f"(hi));
    return d;
}
__device__ __forceinline__ void unpack2(unsigned long long d, float& lo, float& hi) {
    asm("mov.b64 {%0, %1}, %2;" : "=f"(lo), "=f"(hi) : "l"(d));
}

__global__ __launch_bounds__(256, 1)
void crf_kernel(const float* __restrict__ logits,
                const int*   __restrict__ labels,
                const int*   __restrict__ lens,
                const float* __restrict__ trans,
                float*       __restrict__ out) {
    const int cta  = blockIdx.x;          // 0..127
    const int bA   = d_perm[cta];
    const int bB   = d_perm[Bq - 1 - cta];
    const int lenA = lens[bA];
    const int lenB = lens[bB];
    const int maxlen = (lenA > lenB) ? lenA : lenB;

    const int tid = threadIdx.x;
    const int w   = tid >> 5;
    const int l   = tid & 31;
    const int c   = l >> 3;               // k-chunk (32 cols)
    const int g   = l & 7;                // row-group in warp
    const int rowbase = w * 16 + g * 2;   // this thread's 2 output rows

    __shared__ __align__(128) float abufA[2][LBLq];
    __shared__ __align__(128) float abufB[2][LBLq];
    __shared__ float red[16];

    // ---- expT tile: 2 rows x 32 cols, slot-rotated for bank spread ----
    unsigned long long R2[2][16];
    #pragma unroll
    for (int r = 0; r < 2; ++r) {
        const float* trow = trans + (rowbase + r) * LBLq + c * 32;
        #pragma unroll
        for (int s = 0; s < 8; ++s) {
            const float* src = trow + (((s + c) & 7) << 2);
            R2[r][2 * s]     = pack2(__expf(src[0]), __expf(src[1]));
            R2[r][2 * s + 1] = pack2(__expf(src[2]), __expf(src[3]));
        }
    }
    float vmask[2];
    vmask[0] = (rowbase + 0 < NUMq) ? 1.f : 0.f;
    vmask[1] = (rowbase + 1 < NUMq) ? 1.f : 0.f;
    const int rr0 = (rowbase + 0 < NUMq) ? (rowbase + 0) : (NUMq - 1);
    const int rr1 = (rowbase + 1 < NUMq) ? (rowbase + 1) : (NUMq - 1);

    const int lbA = bA * Tq, lbB = bB * Tq;
    const float* lgA = logits + (size_t)lbA * NUMq;
    const float* lgB = logits + (size_t)lbB * NUMq;

    // ---- gold path scores, both sequences ----
    float gA = 0.f, gB = 0.f;
    for (int t = tid; t < lenA; t += 256) {
        int lab = labels[lbA + t];
        gA += lgA[t * NUMq + lab];
        int prev = (t == 0) ? (LBLq - 2) : labels[lbA + t - 1];
        gA += trans[lab * LBLq + prev];
    }
    for (int t = tid; t < lenB; t += 256) {
        int lab = labels[lbB + t];
        gB += lgB[t * NUMq + lab];
        int prev = (t == 0) ? (LBLq - 2) : labels[lbB + t - 1];
        gB += trans[lab * LBLq + prev];
    }
    if (tid == 0) {
        gA += trans[(LBLq - 1) * LBLq + labels[lbA + lenA - 1]];
        gB += trans[(LBLq - 1) * LBLq + labels[lbB + lenB - 1]];
    }
    #pragma unroll
    for (int d = 16; d >= 1; d >>= 1) {
        gA += __shfl_xor_sync(0xffffffffu, gA, d);
        gB += __shfl_xor_sync(0xffffffffu, gB, d);
    }
    if (l == 0) { red[w] = gA; red[8 + w] = gB; }
    __syncthreads();
    float goldA = 0.f, goldB = 0.f;
    if (tid == 0) {
        #pragma unroll
        for (int k = 0; k < 8; ++k) { goldA += red[k]; goldB += red[8 + k]; }
    }
    __syncthreads();

    // ---- init alpha0 = onehot(start=126) for both ----
    if (tid < LBLq) {
        abufA[0][tid] = (tid == (LBLq - 2)) ? 1.0f : 0.0f;
        abufB[0][tid] = (tid == (LBLq - 2)) ? 1.0f : 0.0f;
    }

    // ---- logit queues (clamped addresses) ----
    float curA[4][2], nxtA[4][2], curB[4][2], nxtB[4][2];
    #pragma unroll
    for (int q = 0; q < 4; ++q) {
        int ta = (q < lenA) ? q : (lenA - 1);
        int tb = (q < lenB) ? q : (lenB - 1);
        curA[q][0] = lgA[ta * NUMq + rr0]; curA[q][1] = lgA[ta * NUMq + rr1];
        curB[q][0] = lgB[tb * NUMq + rr0]; curB[q][1] = lgB[tb * NUMq + rr1];
        int ta2 = (4 + q < lenA) ? (4 + q) : (lenA - 1);
        int tb2 = (4 + q < lenB) ? (4 + q) : (lenB - 1);
        nxtA[q][0] = lgA[ta2 * NUMq + rr0]; nxtA[q][1] = lgA[ta2 * NUMq + rr1];
        nxtB[q][0] = lgB[tb2 * NUMq + rr0]; nxtB[q][1] = lgB[tb2 * NUMq + rr1];
    }

    float logcA = 0.f, invA = 1.f;
    float logcB = 0.f, invB = 1.f;
    __syncthreads();

#define STEP(S, PH, T)                                                          \
    if ((T) < len##S) {                                                         \
        const int rb = (PH) & 1, wb = 1 - rb;                                   \
        const ulonglong2* aa = (const ulonglong2*)(abuf##S[rb] + 32 * c);       \
        unsigned long long a00 = 0ull, a01 = 0ull, a10 = 0ull, a11 = 0ull;      \
        unsigned long long s0 = 0ull, s1 = 0ull;                                \
        _Pragma("unroll")                                                       \
        for (int s = 0; s < 8; ++s) {                                           \
            ulonglong2 A = aa[(s + c) & 7];                                     \
            if ((PH) == 0) { s0 = add2(s0, A.x); s1 = add2(s1, A.y); }          \
            fma2(a00, R2[0][2 * s], A.x); fma2(a01, R2[0][2 * s + 1], A.y);     \
            fma2(a10, R2[1][2 * s], A.x); fma2(a11, R2[1][2 * s + 1], A.y);     \
        }                                                                       \
        if ((PH) == 0) {                                                        \
            float tlo, thi;                                                     \
            unpack2(add2(s0, s1), tlo, thi);                                    \
            float ts = tlo + thi;                                               \
            ts += __shfl_xor_sync(0xffffffffu, ts, 8);                          \
            ts += __shfl_xor_sync(0xffffffffu, ts, 16);                         \
            inv##S   = __fdividef(1.0f, ts);                                    \
            logc##S += __logf(ts);                                              \
            if ((T) != 0) {                                                     \
                _Pragma("unroll")                                               \
                for (int q = 0; q < 4; ++q) {                                   \
                    cur##S[q][0] = nxt##S[q][0];                                \
                    cur##S[q][1] = nxt##S[q][1];                                \
                    int tt = ((T) + 4 + q < len##S) ? ((T) + 4 + q)             \
                                                    : (len##S - 1);             \
                    nxt##S[q][0] = lg##S[tt * NUMq + rr0];                      \
                    nxt##S[q][1] = lg##S[tt * NUMq + rr1];                      \
                }                                                               \
            }                                                                   \
        }                                                                       \
        float lo, hi, ps0, ps1;                                                 \
        unpack2(add2(a00, a01), lo, hi); ps0 = lo + hi;                         \
        ps0 += __shfl_xor_sync(0xffffffffu, ps0, 8);                            \
        ps0 += __shfl_xor_sync(0xffffffffu, ps0, 16);                           \
        unpack2(add2(a10, a11), lo, hi); ps1 = lo + hi;                         \
        ps1 += __shfl_xor_sync(0xffffffffu, ps1, 8);                            \
        ps1 += __shfl_xor_sync(0xffffffffu, ps1, 16);                           \
        float w0 = __expf(cur##S[(PH)][0]) * vmask[0];                          \
        float w1 = __expf(cur##S[(PH)][1]) * vmask[1];                          \
        if ((PH) == 1) { w0 *= inv##S; w1 *= inv##S; }                          \
        if (c == 0)                                                             \
            *(float2*)&abuf##S[wb][rowbase] = make_float2(w0 * ps0, w1 * ps1);  \
    }

    for (int t0 = 0; t0 < maxlen; t0 += 4) {
        STEP(A, 0, t0)     STEP(B, 0, t0)     __syncthreads();
        STEP(A, 1, t0 + 1) STEP(B, 1, t0 + 1) __syncthreads();
        STEP(A, 2, t0 + 2) STEP(B, 2, t0 + 2) __syncthreads();
        STEP(A, 3, t0 + 3) STEP(B, 3, t0 + 3) __syncthreads();
    }
#undef STEP

    // ---- finish both: alpha *= exp(trans[end]); fold pending inv ----
    float fv = 0.f;
    if (tid < LBLq) {
        fv = abufA[lenA & 1][tid] * __expf(trans[(LBLq - 1) * LBLq + tid]);
        if ((lenA & 3) == 1) fv *= invA;
    } else {
        int j2 = tid - LBLq;
        fv = abufB[lenB & 1][j2] * __expf(trans[(LBLq - 1) * LBLq + j2]);
        if ((lenB & 3) == 1) fv *= invB;
    }
    #pragma unroll
    for (int d = 16; d >= 1; d >>= 1)
        fv += __shfl_xor_sync(0xffffffffu, fv, d);
    if (l == 0) red[w] = fv;
    __syncthreads();
    if (tid == 0) {
        float fsA = (red[0] + red[1]) + (red[2] + red[3]);
        float fsB = (red[4] + red[5]) + (red[6] + red[7]);
        out[bA] = goldA - (logcA + __logf(fsA));
        out[bB] = goldB - (logcB + __logf(fsB));
    }
}

extern "C" void kernel_launch(void* const* d_in, const int* in_sizes, int n_in,
                              void* d_out, int out_size) {
    const float* logits = (const float*)d_in[0];
    const int*   labels = (const int*)d_in[1];
    const int*   lens   = (const int*)d_in[2];
    const float* trans  = (const float*)d_in[3];
    float*       out    = (float*)d_out;

    rank_kernel<<<1, Bq>>>(lens);
    crf_kernel<<<Bq / 2, 256>>>(logits, labels, lens, trans, out);
}

// round 9
// speedup vs baseline: 1.5069x; 1.5069x over previous
#include <cuda_runtime.h>

#define Bq   256
#define Tq   1024
#define NUMq 126
#define LBLq 128
#define NSM  152

__device__ int d_perm[Bq];

// Rank sequences by length (desc) so each SM's CTA pair tends to be long+short.
__global__ void rank_kernel(const int* __restrict__ lens) {
    __shared__ int sl[Bq];
    int i = threadIdx.x;
    int li = lens[i];
    sl[i] = li;
    __syncthreads();
    int r = 0;
    #pragma unroll 8
    for (int k = 0; k < Bq; ++k) {
        int lk = sl[k];
        r += (lk > li) || (lk == li && k < i);
    }
    d_perm[r] = i;
}

__device__ __forceinline__ void fma2(unsigned long long& d,
                                     unsigned long long a, unsigned long long b) {
    asm("fma.rn.f32x2 %0, %1, %2, %0;" : "+l"(d) : "l"(a), "l"(b));
}
__device__ __forceinline__ unsigned long long add2(unsigned long long a,
                                                   unsigned long long b) {
    unsigned long long d;
    asm("add.rn.f32x2 %0, %1, %2;" : "=l"(d) : "l"(a), "l"(b));
    return d;
}
__device__ __forceinline__ unsigned long long pack2(float lo, float hi) {
    unsigned long long d;
    asm("mov.b64 %0, {%1, %2};" : "=l"(d) : "f"(lo), "f"(hi));
    return d;
}
__device__ __forceinline__ void unpack2(unsigned long long d, float& lo, float& hi) {
    asm("mov.b64 {%0, %1}, %2;" : "=f"(lo), "=f"(hi) : "l"(d));
}

__global__ __launch_bounds__(128, 2)
void crf_kernel(const float* __restrict__ logits,
                const int*   __restrict__ labels,
                const int*   __restrict__ lens,
                const float* __restrict__ trans,
                float*       __restrict__ out) {
    const int bid  = blockIdx.x;
    const int slot = (bid < NSM) ? bid : (Bq - 1 - (bid - NSM));
    const int b    = d_perm[slot];
    const int len  = lens[b];
    const int tid  = threadIdx.x;
    const int w    = tid >> 5;
    const int l    = tid & 31;
    const int h    = l >> 4;              // k-half (64 cols each)
    const int g    = l & 15;              // row-group within warp
    const int rowbase = w * 32 + g * 2;   // this thread's 2 output rows

    __shared__ __align__(128) float abuf[2][LBLq];  // linear alpha, double buffered
    __shared__ float red[4];

    // ---- expT tile: 2 rows x 64 cols (half h) ----
    unsigned long long R2[2][32];
    #pragma unroll
    for (int r = 0; r < 2; ++r) {
        const float4* trow = (const float4*)(trans + (rowbase + r) * LBLq + h * 64);
        #pragma unroll
        for (int s = 0; s < 16; ++s) {
            float4 v = trow[s];
            R2[r][2 * s]     = pack2(__expf(v.x), __expf(v.y));
            R2[r][2 * s + 1] = pack2(__expf(v.z), __expf(v.w));
        }
    }
    float vmask[2];
    vmask[0] = (rowbase + 0 < NUMq) ? 1.f : 0.f;
    vmask[1] = (rowbase + 1 < NUMq) ? 1.f : 0.f;
    const int rr0 = (rowbase + 0 < NUMq) ? (rowbase + 0) : (NUMq - 1);
    const int rr1 = (rowbase + 1 < NUMq) ? (rowbase + 1) : (NUMq - 1);

    // ---- gold path score (cooperative over t) ----
    const int lb = b * Tq;
    const float* lgb = logits + (size_t)lb * NUMq;
    float gacc = 0.f;
    for (int t = tid; t < len; t += 128) {
        int lab = labels[lb + t];
        gacc += lgb[t * NUMq + lab];
        int prev = (t == 0) ? (LBLq - 2) : labels[lb + t - 1];
        gacc += trans[lab * LBLq + prev];
    }
    if (tid == 0) gacc += trans[(LBLq - 1) * LBLq + labels[lb + len - 1]];
    #pragma unroll
    for (int d = 16; d >= 1; d >>= 1)
        gacc += __shfl_xor_sync(0xffffffffu, gacc, d);
    if (l == 0) red[w] = gacc;
    __syncthreads();
    float gold = 0.f;
    if (tid == 0) gold = (red[0] + red[1]) + (red[2] + red[3]);

    // ---- init alpha0 = onehot(start=126) ----
    abuf[0][tid] = (tid == (LBLq - 2)) ? 1.0f : 0.0f;

    // ---- logit queues + precomputed exp weights for current group ----
    float cur[4][2], nxt[4][2], we[4][2];
    #pragma unroll
    for (int q = 0; q < 4; ++q) {
        int tt = (q < len) ? q : (len - 1);
        cur[q][0] = lgb[tt * NUMq + rr0];
        cur[q][1] = lgb[tt * NUMq + rr1];
        int t2 = (4 + q < len) ? (4 + q) : (len - 1);
        nxt[q][0] = lgb[t2 * NUMq + rr0];
        nxt[q][1] = lgb[t2 * NUMq + rr1];
    }
    #pragma unroll
    for (int q = 0; q < 4; ++q) {
        we[q][0] = __expf(cur[q][0]) * vmask[0];
        we[q][1] = __expf(cur[q][1]) * vmask[1];
    }

    float logc = 0.f;
    float inv  = 1.0f;
    __syncthreads();

#define STEP(PH, T)                                                             \
    {                                                                           \
        const int rb = (PH) & 1, wb = 1 - rb;                                   \
        if ((PH) == 0 && (T) != 0) {                                            \
            _Pragma("unroll")                                                   \
            for (int q = 0; q < 4; ++q) {                                       \
                cur[q][0] = nxt[q][0];                                          \
                cur[q][1] = nxt[q][1];                                          \
                int tt = ((T) + 4 + q < len) ? ((T) + 4 + q) : (len - 1);       \
                nxt[q][0] = lgb[tt * NUMq + rr0];                               \
                nxt[q][1] = lgb[tt * NUMq + rr1];                               \
            }                                                                   \
            _Pragma("unroll")                                                   \
            for (int q = 0; q < 4; ++q) {                                       \
                we[q][0] = __expf(cur[q][0]) * vmask[0];                        \
                we[q][1] = __expf(cur[q][1]) * vmask[1];                        \
            }                                                                   \
        }                                                                       \
        const ulonglong2* aa = (const ulonglong2*)(abuf[rb] + h * 64);          \
        unsigned long long a00 = 0ull, a01 = 0ull, a02 = 0ull, a03 = 0ull;      \
        unsigned long long a10 = 0ull, a11 = 0ull, a12 = 0ull, a13 = 0ull;      \
        unsigned long long s0 = 0ull, s1 = 0ull;                                \
        _Pragma("unroll")                                                       \
        for (int s = 0; s < 16; ++s) {                                          \
            ulonglong2 A = aa[s];                                               \
            if ((PH) == 0) { s0 = add2(s0, A.x); s1 = add2(s1, A.y); }          \
            if (s & 1) {                                                        \
                fma2(a02, R2[0][2 * s], A.x); fma2(a03, R2[0][2 * s + 1], A.y); \
                fma2(a12, R2[1][2 * s], A.x); fma2(a13, R2[1][2 * s + 1], A.y); \
            } else {                                                            \
                fma2(a00, R2[0][2 * s], A.x); fma2(a01, R2[0][2 * s + 1], A.y); \
                fma2(a10, R2[1][2 * s], A.x); fma2(a11, R2[1][2 * s + 1], A.y); \
            }                                                                   \
        }                                                                       \
        if ((PH) == 0) {                                                        \
            float tlo, thi;                                                     \
            unpack2(add2(s0, s1), tlo, thi);                                    \
            float ts = tlo + thi;                                               \
            ts += __shfl_xor_sync(0xffffffffu, ts, 16);                         \
            inv   = __fdividef(1.0f, ts);                                       \
            logc += __logf(ts);                                                 \
        }                                                                       \
        float lo, hi, ps0, ps1;                                                 \
        unpack2(add2(add2(a00, a01), add2(a02, a03)), lo, hi); ps0 = lo + hi;   \
        ps0 += __shfl_xor_sync(0xffffffffu, ps0, 16);                           \
        unpack2(add2(add2(a10, a11), add2(a12, a13)), lo, hi); ps1 = lo + hi;   \
        ps1 += __shfl_xor_sync(0xffffffffu, ps1, 16);                           \
        float w0 = we[(PH)][0], w1 = we[(PH)][1];                               \
        if ((PH) == 1) { w0 *= inv; w1 *= inv; }                                \
        if (h == 0)                                                             \
            *(float2*)&abuf[wb][rowbase] = make_float2(w0 * ps0, w1 * ps1);     \
        __syncthreads();                                                        \
    }

    int t0 = 0;
    for (; t0 + 4 <= len; t0 += 4) {
        STEP(0, t0)
        STEP(1, t0 + 1)
        STEP(2, t0 + 2)
        STEP(3, t0 + 3)
    }
    const int rem = len - t0;
    if (rem > 0) STEP(0, t0)
    if (rem > 1) STEP(1, t0 + 1)
    if (rem > 2) STEP(2, t0 + 2)
#undef STEP

    // ---- finish: alpha *= exp(trans[end]); fold pending inv if the sequence
    // ended right after a group head (inv computed but never applied).
    const int rbf = len & 1;
    float fv = abuf[rbf][tid] * __expf(trans[(LBLq - 1) * LBLq + tid]);
    if ((len & 3) == 1) fv *= inv;
    #pragma unroll
    for (int d = 16; d >= 1; d >>= 1)
        fv += __shfl_xor_sync(0xffffffffu, fv, d);
    if (l == 0) red[w] = fv;
    __syncthreads();
    if (tid == 0) {
        float fs = (red[0] + red[1]) + (red[2] + red[3]);
        out[b] = gold - (logc + __logf(fs));
    }
}

extern "C" void kernel_launch(void* const* d_in, const int* in_sizes, int n_in,
                              void* d_out, int out_size) {
    const float* logits = (const float*)d_in[0];
    const int*   labels = (const int*)d_in[1];
    const int*   lens   = (const int*)d_in[2];
    const float* trans  = (const float*)d_in[3];
    float*       out    = (float*)d_out;

    rank_kernel<<<1, Bq>>>(lens);
    crf_kernel<<<Bq, 128>>>(logits, labels, lens, trans, out);
}